// round 1
// baseline (speedup 1.0000x reference)
#include <cuda_runtime.h>
#include <math.h>

#define D_MODEL   1024
#define NUM_HEADS 16
#define HEAD_DIM  64
#define BATCH     2
#define SEQ       2048
#define M_ROWS    (BATCH * SEQ)          // 4096
#define QKV_N     (3 * D_MODEL)          // 3072

// ---------------- scratch (allocation-free: __device__ globals) ----------------
__device__ float g_q[BATCH * NUM_HEADS * SEQ * HEAD_DIM];   // [B,H,S,hd] 16MB
__device__ float g_k[BATCH * NUM_HEADS * SEQ * HEAD_DIM];
__device__ float g_v[BATCH * NUM_HEADS * SEQ * HEAD_DIM];
__device__ float g_ctx[M_ROWS * D_MODEL];                   // [B,S,D]    16MB

// =======================================================================
// GEMM: C[M,N] = A[M,K] @ W[N,K]^T + bias[N]
// MODE 1: A = x (param), epilogue scatters into g_q/g_k/g_v ([B,H,S,hd])
// MODE 2: A = g_ctx (global), epilogue writes C (param) row-major
// Tiles: BM=BN=64, BK=16, 256 threads, 4x4 per-thread micro-tile.
// =======================================================================
#define GPAD 68

template <int MODE>
__global__ __launch_bounds__(256)
void gemm_kernel(const float* __restrict__ A,
                 const float* __restrict__ W,
                 const float* __restrict__ bias,
                 float* __restrict__ C,
                 int M, int N, int K)
{
    __shared__ float As[16 * GPAD];   // [kk][row]
    __shared__ float Ws[16 * GPAD];   // [kk][col]

    const int tid = threadIdx.x;
    const int tx  = tid & 15;          // 0..15 -> 4 cols each
    const int ty  = tid >> 4;          // 0..15 -> 4 rows each
    const int m0  = blockIdx.y * 64;
    const int n0  = blockIdx.x * 64;

    const float* Abase = (MODE == 2) ? (const float*)g_ctx : A;

    // loader mapping: each thread loads one float4 per tile per matrix
    const int lr = tid >> 2;           // 0..63 (tile row)
    const int lc = (tid & 3) << 2;     // 0,4,8,12 (k offset)

    const float* Ap = Abase + (size_t)(m0 + lr) * K + lc;
    const float* Wp = W     + (size_t)(n0 + lr) * K + lc;

    float acc[4][4];
#pragma unroll
    for (int i = 0; i < 4; ++i)
#pragma unroll
        for (int j = 0; j < 4; ++j) acc[i][j] = 0.f;

    for (int k0 = 0; k0 < K; k0 += 16) {
        float4 av = *(const float4*)(Ap + k0);
        float4 wv = *(const float4*)(Wp + k0);
        As[(lc + 0) * GPAD + lr] = av.x;
        As[(lc + 1) * GPAD + lr] = av.y;
        As[(lc + 2) * GPAD + lr] = av.z;
        As[(lc + 3) * GPAD + lr] = av.w;
        Ws[(lc + 0) * GPAD + lr] = wv.x;
        Ws[(lc + 1) * GPAD + lr] = wv.y;
        Ws[(lc + 2) * GPAD + lr] = wv.z;
        Ws[(lc + 3) * GPAD + lr] = wv.w;
        __syncthreads();

#pragma unroll
        for (int kk = 0; kk < 16; ++kk) {
            float a_[4], b_[4];
#pragma unroll
            for (int i = 0; i < 4; ++i) a_[i] = As[kk * GPAD + ty * 4 + i];
#pragma unroll
            for (int j = 0; j < 4; ++j) b_[j] = Ws[kk * GPAD + tx * 4 + j];
#pragma unroll
            for (int i = 0; i < 4; ++i)
#pragma unroll
                for (int j = 0; j < 4; ++j)
                    acc[i][j] = fmaf(a_[i], b_[j], acc[i][j]);
        }
        __syncthreads();
    }

    // epilogue
    const int ncol = n0 + tx * 4;
    float b4[4];
#pragma unroll
    for (int j = 0; j < 4; ++j) b4[j] = bias[ncol + j];

    if (MODE == 1) {
        // scatter into q/k/v [B,H,S,hd]
        const int which = ncol >> 10;          // 0=q,1=k,2=v
        const int din   = ncol & 1023;
        const int h     = din >> 6;
        const int dd    = din & 63;
        float* dst = (which == 0) ? g_q : (which == 1) ? g_k : g_v;
#pragma unroll
        for (int i = 0; i < 4; ++i) {
            const int m = m0 + ty * 4 + i;
            const int b = m >> 11;
            const int s = m & 2047;
            float4 o = make_float4(acc[i][0] + b4[0], acc[i][1] + b4[1],
                                   acc[i][2] + b4[2], acc[i][3] + b4[3]);
            *(float4*)&dst[((size_t)(b * NUM_HEADS + h) * SEQ + s) * HEAD_DIM + dd] = o;
        }
    } else {
#pragma unroll
        for (int i = 0; i < 4; ++i) {
            const int m = m0 + ty * 4 + i;
            float4 o = make_float4(acc[i][0] + b4[0], acc[i][1] + b4[1],
                                   acc[i][2] + b4[2], acc[i][3] + b4[3]);
            *(float4*)&C[(size_t)m * N + ncol] = o;
        }
    }
}

// =======================================================================
// Flash attention (fp32, causal). One CTA per (b,h, 64-row q tile).
// 256 threads; score tile 64x64 -> 4x4 per thread; PV acc 64x64 -> 4x4.
// =======================================================================
#define APAD 68
#define ATTN_SMEM (4 * 64 * APAD * sizeof(float))   // Qs,Ks,Vs,Ps = 69632 B

__global__ __launch_bounds__(256)
void attn_kernel()
{
    extern __shared__ float sm[];
    float* Qs = sm;                 // [d][qrow]   (transposed)
    float* Ks = sm + 64 * APAD;     // [d][kcol]   (transposed)
    float* Vs = sm + 2 * 64 * APAD; // [k][d]
    float* Ps = sm + 3 * 64 * APAD; // [qrow][kcol]

    const int tid = threadIdx.x;
    const int tx  = tid & 15;
    const int ty  = tid >> 4;
    const int qt  = blockIdx.x;     // q tile index (0..31)
    const int bh  = blockIdx.y;     // 0..31
    const int q0  = qt * 64;

    const float* qp = g_q + (size_t)bh * SEQ * HEAD_DIM;
    const float* kp = g_k + (size_t)bh * SEQ * HEAD_DIM;
    const float* vp = g_v + (size_t)bh * SEQ * HEAD_DIM;

    // loaders: 256 threads, each covers rows tid>>4 step 16, 4 dims
    const int lr = tid >> 4;          // 0..15
    const int lc = (tid & 15) << 2;   // 0..60

    // load Q tile transposed: Qs[d][row]
    for (int r = lr; r < 64; r += 16) {
        float4 v = *(const float4*)(qp + (size_t)(q0 + r) * HEAD_DIM + lc);
        Qs[(lc + 0) * APAD + r] = v.x;
        Qs[(lc + 1) * APAD + r] = v.y;
        Qs[(lc + 2) * APAD + r] = v.z;
        Qs[(lc + 3) * APAD + r] = v.w;
    }

    float acc[4][4];
    float mrow[4], lrow[4];
#pragma unroll
    for (int i = 0; i < 4; ++i) {
        mrow[i] = -INFINITY;
        lrow[i] = 0.f;
#pragma unroll
        for (int j = 0; j < 4; ++j) acc[i][j] = 0.f;
    }

    const float scale = 0.125f;  // hd^-0.5

    for (int t = 0; t <= qt; ++t) {
        __syncthreads();  // prev PV done reading Ps/Vs (iter0: no-op hazard-wise)

        // load K tile transposed + V tile natural
        for (int r = lr; r < 64; r += 16) {
            float4 kv = *(const float4*)(kp + (size_t)(t * 64 + r) * HEAD_DIM + lc);
            Ks[(lc + 0) * APAD + r] = kv.x;
            Ks[(lc + 1) * APAD + r] = kv.y;
            Ks[(lc + 2) * APAD + r] = kv.z;
            Ks[(lc + 3) * APAD + r] = kv.w;
            float4 vv = *(const float4*)(vp + (size_t)(t * 64 + r) * HEAD_DIM + lc);
            *(float4*)&Vs[r * APAD + lc] = vv;
        }
        __syncthreads();  // also guarantees Qs visible on iter 0

        // S = Q @ K^T
        float sc[4][4];
#pragma unroll
        for (int i = 0; i < 4; ++i)
#pragma unroll
            for (int j = 0; j < 4; ++j) sc[i][j] = 0.f;

#pragma unroll 16
        for (int kk = 0; kk < 64; ++kk) {
            float a_[4], b_[4];
#pragma unroll
            for (int i = 0; i < 4; ++i) a_[i] = Qs[kk * APAD + ty * 4 + i];
#pragma unroll
            for (int j = 0; j < 4; ++j) b_[j] = Ks[kk * APAD + tx * 4 + j];
#pragma unroll
            for (int i = 0; i < 4; ++i)
#pragma unroll
                for (int j = 0; j < 4; ++j)
                    sc[i][j] = fmaf(a_[i], b_[j], sc[i][j]);
        }

        // scale + causal mask (diagonal tile only)
        if (t == qt) {
#pragma unroll
            for (int i = 0; i < 4; ++i) {
                const int qr = ty * 4 + i;
#pragma unroll
                for (int j = 0; j < 4; ++j) {
                    const int kc = tx * 4 + j;
                    sc[i][j] = (kc <= qr) ? sc[i][j] * scale : -INFINITY;
                }
            }
        } else {
#pragma unroll
            for (int i = 0; i < 4; ++i)
#pragma unroll
                for (int j = 0; j < 4; ++j) sc[i][j] *= scale;
        }

        // online softmax (row reductions across the 16 tx lanes)
#pragma unroll
        for (int i = 0; i < 4; ++i) {
            float mt = sc[i][0];
#pragma unroll
            for (int j = 1; j < 4; ++j) mt = fmaxf(mt, sc[i][j]);
#pragma unroll
            for (int off = 8; off >= 1; off >>= 1)
                mt = fmaxf(mt, __shfl_xor_sync(0xffffffffu, mt, off));

            const float mn   = fmaxf(mrow[i], mt);
            const float corr = __expf(mrow[i] - mn);
            float ps = 0.f;
#pragma unroll
            for (int j = 0; j < 4; ++j) {
                const float p = __expf(sc[i][j] - mn);
                sc[i][j] = p;
                ps += p;
            }
#pragma unroll
            for (int off = 8; off >= 1; off >>= 1)
                ps += __shfl_xor_sync(0xffffffffu, ps, off);

            lrow[i] = lrow[i] * corr + ps;
            mrow[i] = mn;
#pragma unroll
            for (int j = 0; j < 4; ++j) acc[i][j] *= corr;

            *(float4*)&Ps[(ty * 4 + i) * APAD + tx * 4] =
                make_float4(sc[i][0], sc[i][1], sc[i][2], sc[i][3]);
        }
        __syncthreads();

        // acc += P @ V
#pragma unroll 16
        for (int kk = 0; kk < 64; ++kk) {
            float p_[4], v_[4];
#pragma unroll
            for (int i = 0; i < 4; ++i) p_[i] = Ps[(ty * 4 + i) * APAD + kk];
#pragma unroll
            for (int j = 0; j < 4; ++j) v_[j] = Vs[kk * APAD + tx * 4 + j];
#pragma unroll
            for (int i = 0; i < 4; ++i)
#pragma unroll
                for (int j = 0; j < 4; ++j)
                    acc[i][j] = fmaf(p_[i], v_[j], acc[i][j]);
        }
    }

    // epilogue -> g_ctx [B,S,D]
    const int b = bh >> 4;
    const int h = bh & 15;
#pragma unroll
    for (int i = 0; i < 4; ++i) {
        const int s = q0 + ty * 4 + i;
        const float inv = 1.f / lrow[i];
        float4 o = make_float4(acc[i][0] * inv, acc[i][1] * inv,
                               acc[i][2] * inv, acc[i][3] * inv);
        *(float4*)&g_ctx[((size_t)(b * SEQ + s)) * D_MODEL + h * HEAD_DIM + tx * 4] = o;
    }
}

// =======================================================================
// launch
// =======================================================================
extern "C" void kernel_launch(void* const* d_in, const int* in_sizes, int n_in,
                              void* d_out, int out_size)
{
    const float* x     = (const float*)d_in[0];
    const float* qkv_w = (const float*)d_in[1];
    const float* qkv_b = (const float*)d_in[2];
    const float* out_w = (const float*)d_in[3];
    const float* out_b = (const float*)d_in[4];
    float* out = (float*)d_out;

    // 1) fused QKV projection + scatter to [B,H,S,hd]
    {
        dim3 grid(QKV_N / 64, M_ROWS / 64);
        gemm_kernel<1><<<grid, 256>>>(x, qkv_w, qkv_b, nullptr,
                                      M_ROWS, QKV_N, D_MODEL);
    }

    // 2) causal flash attention -> g_ctx [B,S,D]
    {
        static int smem_set = 0;
        if (!smem_set) {
            cudaFuncSetAttribute(attn_kernel,
                                 cudaFuncAttributeMaxDynamicSharedMemorySize,
                                 (int)ATTN_SMEM);
            smem_set = 1;
        }
        dim3 grid(SEQ / 64, BATCH * NUM_HEADS);
        attn_kernel<<<grid, 256, ATTN_SMEM>>>();
    }

    // 3) output projection
    {
        dim3 grid(D_MODEL / 64, M_ROWS / 64);
        gemm_kernel<2><<<grid, 256>>>(nullptr, out_w, out_b, out,
                                      M_ROWS, D_MODEL, D_MODEL);
    }
}

// round 3
// speedup vs baseline: 1.6543x; 1.6543x over previous
#include <cuda_runtime.h>
#include <cuda_bf16.h>
#include <stdint.h>
#include <math.h>

#define D_MODEL   1024
#define NUM_HEADS 16
#define HEAD_DIM  64
#define BATCH     2
#define SEQ       2048
#define M_ROWS    (BATCH * SEQ)          // 4096
#define QKV_N     (3 * D_MODEL)          // 3072

// ---------------- scratch (allocation-free: __device__ globals) ----------------
__device__ float g_q[BATCH * NUM_HEADS * SEQ * HEAD_DIM];   // [B,H,S,hd]
__device__ float g_k[BATCH * NUM_HEADS * SEQ * HEAD_DIM];
__device__ float g_v[BATCH * NUM_HEADS * SEQ * HEAD_DIM];
__device__ float g_ctx[M_ROWS * D_MODEL];                   // [B,S,D]

__device__ __forceinline__ uint32_t smem_u32(const void* p) {
    uint32_t a;
    asm("{ .reg .u64 t; cvta.to.shared.u64 t, %1; cvt.u32.u64 %0, t; }"
        : "=r"(a) : "l"(p));
    return a;
}

__device__ __forceinline__ void ldmx4(uint32_t* r, uint32_t addr) {
    asm volatile("ldmatrix.sync.aligned.m8n8.x4.shared.b16 {%0,%1,%2,%3}, [%4];"
                 : "=r"(r[0]), "=r"(r[1]), "=r"(r[2]), "=r"(r[3]) : "r"(addr));
}

__device__ __forceinline__ void mma_bf16(float* c, const uint32_t* a,
                                         uint32_t b0, uint32_t b1) {
    asm volatile(
        "mma.sync.aligned.m16n8k16.row.col.f32.bf16.bf16.f32 "
        "{%0,%1,%2,%3}, {%4,%5,%6,%7}, {%8,%9}, {%0,%1,%2,%3};"
        : "+f"(c[0]), "+f"(c[1]), "+f"(c[2]), "+f"(c[3])
        : "r"(a[0]), "r"(a[1]), "r"(a[2]), "r"(a[3]), "r"(b0), "r"(b1));
}

// split fp32 -> (hi, lo) bf16 pairs, packed 4 elems -> uint2 each
__device__ __forceinline__ void cvt_split(float4 v, uint2& hi, uint2& lo) {
    __nv_bfloat162 h01 = __floats2bfloat162_rn(v.x, v.y);
    __nv_bfloat162 h23 = __floats2bfloat162_rn(v.z, v.w);
    float2 f01 = __bfloat1622float2(h01);
    float2 f23 = __bfloat1622float2(h23);
    __nv_bfloat162 l01 = __floats2bfloat162_rn(v.x - f01.x, v.y - f01.y);
    __nv_bfloat162 l23 = __floats2bfloat162_rn(v.z - f23.x, v.w - f23.y);
    hi = make_uint2(*(uint32_t*)&h01, *(uint32_t*)&h23);
    lo = make_uint2(*(uint32_t*)&l01, *(uint32_t*)&l23);
}

// =======================================================================
// HMMA GEMM: C[M,N] = A[M,K] @ W[N,K]^T + bias, split-bf16 (3 MMAs)
// CTA tile 128x128, BK=32, 256 threads (8 warps, warp tile 64x32).
// MODE 1: A = x, scatter epilogue to g_q/g_k/g_v.  MODE 2: A = g_ctx -> C.
// =======================================================================
#define LDA   40                          // bf16 elems per smem row (32+8 pad)
#define SUB_E (128 * LDA)                 // 5120 bf16 elems per sub-tile
#define STAGE_B (4 * SUB_E * 2)           // 40960 bytes (Ahi,Alo,Whi,Wlo)
#define HG_SMEM (2 * STAGE_B)             // 81920

template <int MODE>
__global__ __launch_bounds__(256, 1)
void hgemm(const float* __restrict__ A,
           const float* __restrict__ W,
           const float* __restrict__ bias,
           float* __restrict__ C,
           int N, int K)
{
    extern __shared__ char sm[];
    const uint32_t sb = smem_u32(sm);
    const int tid  = threadIdx.x;
    const int lane = tid & 31;
    const int wid  = tid >> 5;
    const int wm   = wid & 1;             // 2 warp-rows of 64
    const int wn   = wid >> 1;            // 4 warp-cols of 32
    const int m0   = blockIdx.y * 128;
    const int n0   = blockIdx.x * 128;

    const float* Abase = (MODE == 2) ? (const float*)g_ctx : A;

    float acc[4][4][4];
#pragma unroll
    for (int mt = 0; mt < 4; ++mt)
#pragma unroll
        for (int nt = 0; nt < 4; ++nt)
#pragma unroll
            for (int r = 0; r < 4; ++r) acc[mt][nt][r] = 0.f;

    // loader mapping: 4 float4 each for A and W per iter
    int lrow[4], lc4[4];
#pragma unroll
    for (int r = 0; r < 4; ++r) {
        const int idx = r * 256 + tid;     // 0..1023
        lrow[r] = idx >> 3;                // 0..127
        lc4[r]  = idx & 7;                 // 0..7 (float4 col)
    }

    const int niters = K / 32;
    float4 pa[4], pw[4];

    // prologue: load + stage 0
#pragma unroll
    for (int r = 0; r < 4; ++r) {
        pa[r] = *(const float4*)(Abase + (size_t)(m0 + lrow[r]) * K + lc4[r] * 4);
        pw[r] = *(const float4*)(W     + (size_t)(n0 + lrow[r]) * K + lc4[r] * 4);
    }
    {
        __nv_bfloat16* st = (__nv_bfloat16*)sm;   // stage 0
#pragma unroll
        for (int r = 0; r < 4; ++r) {
            uint2 hi, lo;
            const int off = lrow[r] * LDA + lc4[r] * 4;
            cvt_split(pa[r], hi, lo);
            *(uint2*)(st + 0 * SUB_E + off) = hi;
            *(uint2*)(st + 1 * SUB_E + off) = lo;
            cvt_split(pw[r], hi, lo);
            *(uint2*)(st + 2 * SUB_E + off) = hi;
            *(uint2*)(st + 3 * SUB_E + off) = lo;
        }
    }
    __syncthreads();

    // ldmatrix lane addressing (element offsets within a sub-tile)
    const int a_eoff = (wm * 64 + (lane & 15)) * LDA + ((lane >> 4) << 3);
    const int b_eoff = (wn * 32 + (lane & 7) + ((lane >> 4) & 1) * 8) * LDA
                     + (((lane >> 3) & 1) << 3);

    for (int i = 0; i < niters; ++i) {
        const int s = i & 1;
        const uint32_t stage_u = sb + s * STAGE_B;

        // prefetch next tile into registers
        if (i + 1 < niters) {
            const int k0 = (i + 1) * 32;
#pragma unroll
            for (int r = 0; r < 4; ++r) {
                pa[r] = *(const float4*)(Abase + (size_t)(m0 + lrow[r]) * K + k0 + lc4[r] * 4);
                pw[r] = *(const float4*)(W     + (size_t)(n0 + lrow[r]) * K + k0 + lc4[r] * 4);
            }
        }

        // compute on stage s
#pragma unroll
        for (int ks = 0; ks < 2; ++ks) {
            uint32_t ah[4][4], al[4][4];
#pragma unroll
            for (int mt = 0; mt < 4; ++mt) {
                const uint32_t ao = (uint32_t)((a_eoff + mt * 16 * LDA + ks * 16) * 2);
                ldmx4(ah[mt], stage_u + 0 * SUB_E * 2 + ao);
                ldmx4(al[mt], stage_u + 1 * SUB_E * 2 + ao);
            }
#pragma unroll
            for (int g = 0; g < 2; ++g) {
                uint32_t bh[4], bl[4];
                const uint32_t bo = (uint32_t)((b_eoff + g * 16 * LDA + ks * 16) * 2);
                ldmx4(bh, stage_u + 2 * SUB_E * 2 + bo);
                ldmx4(bl, stage_u + 3 * SUB_E * 2 + bo);
#pragma unroll
                for (int mt = 0; mt < 4; ++mt) {
                    mma_bf16(acc[mt][2 * g],     ah[mt], bh[0], bh[1]);
                    mma_bf16(acc[mt][2 * g],     ah[mt], bl[0], bl[1]);
                    mma_bf16(acc[mt][2 * g],     al[mt], bh[0], bh[1]);
                    mma_bf16(acc[mt][2 * g + 1], ah[mt], bh[2], bh[3]);
                    mma_bf16(acc[mt][2 * g + 1], ah[mt], bl[2], bl[3]);
                    mma_bf16(acc[mt][2 * g + 1], al[mt], bh[2], bh[3]);
                }
            }
        }

        // stage next tile
        if (i + 1 < niters) {
            __nv_bfloat16* st = (__nv_bfloat16*)(sm + (s ^ 1) * STAGE_B);
#pragma unroll
            for (int r = 0; r < 4; ++r) {
                uint2 hi, lo;
                const int off = lrow[r] * LDA + lc4[r] * 4;
                cvt_split(pa[r], hi, lo);
                *(uint2*)(st + 0 * SUB_E + off) = hi;
                *(uint2*)(st + 1 * SUB_E + off) = lo;
                cvt_split(pw[r], hi, lo);
                *(uint2*)(st + 2 * SUB_E + off) = hi;
                *(uint2*)(st + 3 * SUB_E + off) = lo;
            }
        }
        __syncthreads();
    }

    // epilogue: fragment -> global (fp32, +bias)
#pragma unroll
    for (int mt = 0; mt < 4; ++mt) {
        const int row = m0 + wm * 64 + mt * 16 + (lane >> 2);
#pragma unroll
        for (int nt = 0; nt < 4; ++nt) {
            const int col = n0 + wn * 32 + nt * 8 + ((lane & 3) << 1);
            float2 bb = *(const float2*)&bias[col];
            float2 o0 = make_float2(acc[mt][nt][0] + bb.x, acc[mt][nt][1] + bb.y);
            float2 o1 = make_float2(acc[mt][nt][2] + bb.x, acc[mt][nt][3] + bb.y);
            if (MODE == 1) {
                const int which = col >> 10;
                const int h  = (col >> 6) & 15;
                const int dd = col & 63;
                float* dst = (which == 0) ? g_q : (which == 1) ? g_k : g_v;
                const int b0i = row >> 11, s0i = row & 2047;
                *(float2*)&dst[((size_t)((b0i << 4) + h) * SEQ + s0i) * HEAD_DIM + dd] = o0;
                const int r1 = row + 8;
                const int b1i = r1 >> 11, s1i = r1 & 2047;
                *(float2*)&dst[((size_t)((b1i << 4) + h) * SEQ + s1i) * HEAD_DIM + dd] = o1;
            } else {
                *(float2*)&C[(size_t)row * N + col] = o0;
                *(float2*)&C[(size_t)(row + 8) * N + col] = o1;
            }
        }
    }
}

// =======================================================================
// Flash attention (fp32, causal) — unchanged (known good)
// =======================================================================
#define APAD 68
#define ATTN_SMEM (4 * 64 * APAD * sizeof(float))

__global__ __launch_bounds__(256)
void attn_kernel()
{
    extern __shared__ float smf[];
    float* Qs = smf;
    float* Ks = smf + 64 * APAD;
    float* Vs = smf + 2 * 64 * APAD;
    float* Ps = smf + 3 * 64 * APAD;

    const int tid = threadIdx.x;
    const int tx  = tid & 15;
    const int ty  = tid >> 4;
    const int qt  = blockIdx.x;
    const int bh  = blockIdx.y;
    const int q0  = qt * 64;

    const float* qp = g_q + (size_t)bh * SEQ * HEAD_DIM;
    const float* kp = g_k + (size_t)bh * SEQ * HEAD_DIM;
    const float* vp = g_v + (size_t)bh * SEQ * HEAD_DIM;

    const int lr = tid >> 4;
    const int lc = (tid & 15) << 2;

    for (int r = lr; r < 64; r += 16) {
        float4 v = *(const float4*)(qp + (size_t)(q0 + r) * HEAD_DIM + lc);
        Qs[(lc + 0) * APAD + r] = v.x;
        Qs[(lc + 1) * APAD + r] = v.y;
        Qs[(lc + 2) * APAD + r] = v.z;
        Qs[(lc + 3) * APAD + r] = v.w;
    }

    float acc[4][4];
    float mrow[4], lrow[4];
#pragma unroll
    for (int i = 0; i < 4; ++i) {
        mrow[i] = -INFINITY;
        lrow[i] = 0.f;
#pragma unroll
        for (int j = 0; j < 4; ++j) acc[i][j] = 0.f;
    }

    const float scale = 0.125f;

    for (int t = 0; t <= qt; ++t) {
        __syncthreads();
        for (int r = lr; r < 64; r += 16) {
            float4 kv = *(const float4*)(kp + (size_t)(t * 64 + r) * HEAD_DIM + lc);
            Ks[(lc + 0) * APAD + r] = kv.x;
            Ks[(lc + 1) * APAD + r] = kv.y;
            Ks[(lc + 2) * APAD + r] = kv.z;
            Ks[(lc + 3) * APAD + r] = kv.w;
            float4 vv = *(const float4*)(vp + (size_t)(t * 64 + r) * HEAD_DIM + lc);
            *(float4*)&Vs[r * APAD + lc] = vv;
        }
        __syncthreads();

        float sc[4][4];
#pragma unroll
        for (int i = 0; i < 4; ++i)
#pragma unroll
            for (int j = 0; j < 4; ++j) sc[i][j] = 0.f;

#pragma unroll 16
        for (int kk = 0; kk < 64; ++kk) {
            float a_[4], b_[4];
#pragma unroll
            for (int i = 0; i < 4; ++i) a_[i] = Qs[kk * APAD + ty * 4 + i];
#pragma unroll
            for (int j = 0; j < 4; ++j) b_[j] = Ks[kk * APAD + tx * 4 + j];
#pragma unroll
            for (int i = 0; i < 4; ++i)
#pragma unroll
                for (int j = 0; j < 4; ++j)
                    sc[i][j] = fmaf(a_[i], b_[j], sc[i][j]);
        }

        if (t == qt) {
#pragma unroll
            for (int i = 0; i < 4; ++i) {
                const int qr = ty * 4 + i;
#pragma unroll
                for (int j = 0; j < 4; ++j) {
                    const int kc = tx * 4 + j;
                    sc[i][j] = (kc <= qr) ? sc[i][j] * scale : -INFINITY;
                }
            }
        } else {
#pragma unroll
            for (int i = 0; i < 4; ++i)
#pragma unroll
                for (int j = 0; j < 4; ++j) sc[i][j] *= scale;
        }

#pragma unroll
        for (int i = 0; i < 4; ++i) {
            float mt = sc[i][0];
#pragma unroll
            for (int j = 1; j < 4; ++j) mt = fmaxf(mt, sc[i][j]);
#pragma unroll
            for (int off = 8; off >= 1; off >>= 1)
                mt = fmaxf(mt, __shfl_xor_sync(0xffffffffu, mt, off));

            const float mn   = fmaxf(mrow[i], mt);
            const float corr = __expf(mrow[i] - mn);
            float ps = 0.f;
#pragma unroll
            for (int j = 0; j < 4; ++j) {
                const float p = __expf(sc[i][j] - mn);
                sc[i][j] = p;
                ps += p;
            }
#pragma unroll
            for (int off = 8; off >= 1; off >>= 1)
                ps += __shfl_xor_sync(0xffffffffu, ps, off);

            lrow[i] = lrow[i] * corr + ps;
            mrow[i] = mn;
#pragma unroll
            for (int j = 0; j < 4; ++j) acc[i][j] *= corr;

            *(float4*)&Ps[(ty * 4 + i) * APAD + tx * 4] =
                make_float4(sc[i][0], sc[i][1], sc[i][2], sc[i][3]);
        }
        __syncthreads();

#pragma unroll 16
        for (int kk = 0; kk < 64; ++kk) {
            float p_[4], v_[4];
#pragma unroll
            for (int i = 0; i < 4; ++i) p_[i] = Ps[(ty * 4 + i) * APAD + kk];
#pragma unroll
            for (int j = 0; j < 4; ++j) v_[j] = Vs[kk * APAD + tx * 4 + j];
#pragma unroll
            for (int i = 0; i < 4; ++i)
#pragma unroll
                for (int j = 0; j < 4; ++j)
                    acc[i][j] = fmaf(p_[i], v_[j], acc[i][j]);
        }
    }

    const int b = bh >> 4;
    const int h = bh & 15;
#pragma unroll
    for (int i = 0; i < 4; ++i) {
        const int s = q0 + ty * 4 + i;
        const float inv = 1.f / lrow[i];
        float4 o = make_float4(acc[i][0] * inv, acc[i][1] * inv,
                               acc[i][2] * inv, acc[i][3] * inv);
        *(float4*)&g_ctx[((size_t)(b * SEQ + s)) * D_MODEL + h * HEAD_DIM + tx * 4] = o;
    }
}

// =======================================================================
// launch
// =======================================================================
extern "C" void kernel_launch(void* const* d_in, const int* in_sizes, int n_in,
                              void* d_out, int out_size)
{
    const float* x     = (const float*)d_in[0];
    const float* qkv_w = (const float*)d_in[1];
    const float* qkv_b = (const float*)d_in[2];
    const float* out_w = (const float*)d_in[3];
    const float* out_b = (const float*)d_in[4];
    float* out = (float*)d_out;

    static int attr_set = 0;
    if (!attr_set) {
        cudaFuncSetAttribute(hgemm<1>, cudaFuncAttributeMaxDynamicSharedMemorySize, HG_SMEM);
        cudaFuncSetAttribute(hgemm<2>, cudaFuncAttributeMaxDynamicSharedMemorySize, HG_SMEM);
        cudaFuncSetAttribute(attn_kernel, cudaFuncAttributeMaxDynamicSharedMemorySize, (int)ATTN_SMEM);
        attr_set = 1;
    }

    // 1) QKV projection (HMMA split-bf16) + scatter to [B,H,S,hd]
    {
        dim3 grid(QKV_N / 128, M_ROWS / 128);
        hgemm<1><<<grid, 256, HG_SMEM>>>(x, qkv_w, qkv_b, nullptr, QKV_N, D_MODEL);
    }

    // 2) causal flash attention -> g_ctx [B,S,D]
    {
        dim3 grid(SEQ / 64, BATCH * NUM_HEADS);
        attn_kernel<<<grid, 256, ATTN_SMEM>>>();
    }

    // 3) output projection (HMMA split-bf16)
    {
        dim3 grid(D_MODEL / 128, M_ROWS / 128);
        hgemm<2><<<grid, 256, HG_SMEM>>>(nullptr, out_w, out_b, out, D_MODEL, D_MODEL);
    }
}

// round 4
// speedup vs baseline: 3.0591x; 1.8492x over previous
#include <cuda_runtime.h>
#include <cuda_bf16.h>
#include <stdint.h>
#include <math.h>

#define D_MODEL   1024
#define NUM_HEADS 16
#define HEAD_DIM  64
#define BATCH     2
#define SEQ       2048
#define M_ROWS    (BATCH * SEQ)          // 4096
#define QKV_N     (3 * D_MODEL)          // 3072

// ---------------- scratch (allocation-free: __device__ globals) ----------------
__device__ float g_q[BATCH * NUM_HEADS * SEQ * HEAD_DIM];   // [B,H,S,hd]
__device__ float g_k[BATCH * NUM_HEADS * SEQ * HEAD_DIM];
__device__ float g_v[BATCH * NUM_HEADS * SEQ * HEAD_DIM];
__device__ float g_ctx[M_ROWS * D_MODEL];                   // [B,S,D]

__device__ __forceinline__ uint32_t smem_u32(const void* p) {
    uint32_t a;
    asm("{ .reg .u64 t; cvta.to.shared.u64 t, %1; cvt.u32.u64 %0, t; }"
        : "=r"(a) : "l"(p));
    return a;
}

__device__ __forceinline__ void ldmx4(uint32_t* r, uint32_t addr) {
    asm volatile("ldmatrix.sync.aligned.m8n8.x4.shared.b16 {%0,%1,%2,%3}, [%4];"
                 : "=r"(r[0]), "=r"(r[1]), "=r"(r[2]), "=r"(r[3]) : "r"(addr));
}

__device__ __forceinline__ void ldmx4t(uint32_t* r, uint32_t addr) {
    asm volatile("ldmatrix.sync.aligned.m8n8.x4.trans.shared.b16 {%0,%1,%2,%3}, [%4];"
                 : "=r"(r[0]), "=r"(r[1]), "=r"(r[2]), "=r"(r[3]) : "r"(addr));
}

__device__ __forceinline__ void mma_bf16(float* c, const uint32_t* a,
                                         uint32_t b0, uint32_t b1) {
    asm volatile(
        "mma.sync.aligned.m16n8k16.row.col.f32.bf16.bf16.f32 "
        "{%0,%1,%2,%3}, {%4,%5,%6,%7}, {%8,%9}, {%0,%1,%2,%3};"
        : "+f"(c[0]), "+f"(c[1]), "+f"(c[2]), "+f"(c[3])
        : "r"(a[0]), "r"(a[1]), "r"(a[2]), "r"(a[3]), "r"(b0), "r"(b1));
}

// split fp32 -> (hi, lo) bf16 pairs, packed 4 elems -> uint2 each
__device__ __forceinline__ void cvt_split(float4 v, uint2& hi, uint2& lo) {
    __nv_bfloat162 h01 = __floats2bfloat162_rn(v.x, v.y);
    __nv_bfloat162 h23 = __floats2bfloat162_rn(v.z, v.w);
    float2 f01 = __bfloat1622float2(h01);
    float2 f23 = __bfloat1622float2(h23);
    __nv_bfloat162 l01 = __floats2bfloat162_rn(v.x - f01.x, v.y - f01.y);
    __nv_bfloat162 l23 = __floats2bfloat162_rn(v.z - f23.x, v.w - f23.y);
    hi = make_uint2(*(uint32_t*)&h01, *(uint32_t*)&h23);
    lo = make_uint2(*(uint32_t*)&l01, *(uint32_t*)&l23);
}

__device__ __forceinline__ void pack_split2(float x, float y, uint32_t& hi, uint32_t& lo) {
    __nv_bfloat162 h = __floats2bfloat162_rn(x, y);
    float2 f = __bfloat1622float2(h);
    __nv_bfloat162 l = __floats2bfloat162_rn(x - f.x, y - f.y);
    hi = *(uint32_t*)&h;
    lo = *(uint32_t*)&l;
}

// =======================================================================
// HMMA GEMM (unchanged from round 3, known good)
// =======================================================================
#define LDA   40
#define SUB_E (128 * LDA)
#define STAGE_B (4 * SUB_E * 2)
#define HG_SMEM (2 * STAGE_B)

template <int MODE>
__global__ __launch_bounds__(256, 1)
void hgemm(const float* __restrict__ A,
           const float* __restrict__ W,
           const float* __restrict__ bias,
           float* __restrict__ C,
           int N, int K)
{
    extern __shared__ char sm[];
    const uint32_t sb = smem_u32(sm);
    const int tid  = threadIdx.x;
    const int lane = tid & 31;
    const int wid  = tid >> 5;
    const int wm   = wid & 1;
    const int wn   = wid >> 1;
    const int m0   = blockIdx.y * 128;
    const int n0   = blockIdx.x * 128;

    const float* Abase = (MODE == 2) ? (const float*)g_ctx : A;

    float acc[4][4][4];
#pragma unroll
    for (int mt = 0; mt < 4; ++mt)
#pragma unroll
        for (int nt = 0; nt < 4; ++nt)
#pragma unroll
            for (int r = 0; r < 4; ++r) acc[mt][nt][r] = 0.f;

    int lrow[4], lc4[4];
#pragma unroll
    for (int r = 0; r < 4; ++r) {
        const int idx = r * 256 + tid;
        lrow[r] = idx >> 3;
        lc4[r]  = idx & 7;
    }

    const int niters = K / 32;
    float4 pa[4], pw[4];

#pragma unroll
    for (int r = 0; r < 4; ++r) {
        pa[r] = *(const float4*)(Abase + (size_t)(m0 + lrow[r]) * K + lc4[r] * 4);
        pw[r] = *(const float4*)(W     + (size_t)(n0 + lrow[r]) * K + lc4[r] * 4);
    }
    {
        __nv_bfloat16* st = (__nv_bfloat16*)sm;
#pragma unroll
        for (int r = 0; r < 4; ++r) {
            uint2 hi, lo;
            const int off = lrow[r] * LDA + lc4[r] * 4;
            cvt_split(pa[r], hi, lo);
            *(uint2*)(st + 0 * SUB_E + off) = hi;
            *(uint2*)(st + 1 * SUB_E + off) = lo;
            cvt_split(pw[r], hi, lo);
            *(uint2*)(st + 2 * SUB_E + off) = hi;
            *(uint2*)(st + 3 * SUB_E + off) = lo;
        }
    }
    __syncthreads();

    const int a_eoff = (wm * 64 + (lane & 15)) * LDA + ((lane >> 4) << 3);
    const int b_eoff = (wn * 32 + (lane & 7) + ((lane >> 4) & 1) * 8) * LDA
                     + (((lane >> 3) & 1) << 3);

    for (int i = 0; i < niters; ++i) {
        const int s = i & 1;
        const uint32_t stage_u = sb + s * STAGE_B;

        if (i + 1 < niters) {
            const int k0 = (i + 1) * 32;
#pragma unroll
            for (int r = 0; r < 4; ++r) {
                pa[r] = *(const float4*)(Abase + (size_t)(m0 + lrow[r]) * K + k0 + lc4[r] * 4);
                pw[r] = *(const float4*)(W     + (size_t)(n0 + lrow[r]) * K + k0 + lc4[r] * 4);
            }
        }

#pragma unroll
        for (int ks = 0; ks < 2; ++ks) {
            uint32_t ah[4][4], al[4][4];
#pragma unroll
            for (int mt = 0; mt < 4; ++mt) {
                const uint32_t ao = (uint32_t)((a_eoff + mt * 16 * LDA + ks * 16) * 2);
                ldmx4(ah[mt], stage_u + 0 * SUB_E * 2 + ao);
                ldmx4(al[mt], stage_u + 1 * SUB_E * 2 + ao);
            }
#pragma unroll
            for (int g = 0; g < 2; ++g) {
                uint32_t bh[4], bl[4];
                const uint32_t bo = (uint32_t)((b_eoff + g * 16 * LDA + ks * 16) * 2);
                ldmx4(bh, stage_u + 2 * SUB_E * 2 + bo);
                ldmx4(bl, stage_u + 3 * SUB_E * 2 + bo);
#pragma unroll
                for (int mt = 0; mt < 4; ++mt) {
                    mma_bf16(acc[mt][2 * g],     ah[mt], bh[0], bh[1]);
                    mma_bf16(acc[mt][2 * g],     ah[mt], bl[0], bl[1]);
                    mma_bf16(acc[mt][2 * g],     al[mt], bh[0], bh[1]);
                    mma_bf16(acc[mt][2 * g + 1], ah[mt], bh[2], bh[3]);
                    mma_bf16(acc[mt][2 * g + 1], ah[mt], bl[2], bl[3]);
                    mma_bf16(acc[mt][2 * g + 1], al[mt], bh[2], bh[3]);
                }
            }
        }

        if (i + 1 < niters) {
            __nv_bfloat16* st = (__nv_bfloat16*)(sm + (s ^ 1) * STAGE_B);
#pragma unroll
            for (int r = 0; r < 4; ++r) {
                uint2 hi, lo;
                const int off = lrow[r] * LDA + lc4[r] * 4;
                cvt_split(pa[r], hi, lo);
                *(uint2*)(st + 0 * SUB_E + off) = hi;
                *(uint2*)(st + 1 * SUB_E + off) = lo;
                cvt_split(pw[r], hi, lo);
                *(uint2*)(st + 2 * SUB_E + off) = hi;
                *(uint2*)(st + 3 * SUB_E + off) = lo;
            }
        }
        __syncthreads();
    }

#pragma unroll
    for (int mt = 0; mt < 4; ++mt) {
        const int row = m0 + wm * 64 + mt * 16 + (lane >> 2);
#pragma unroll
        for (int nt = 0; nt < 4; ++nt) {
            const int col = n0 + wn * 32 + nt * 8 + ((lane & 3) << 1);
            float2 bb = *(const float2*)&bias[col];
            float2 o0 = make_float2(acc[mt][nt][0] + bb.x, acc[mt][nt][1] + bb.y);
            float2 o1 = make_float2(acc[mt][nt][2] + bb.x, acc[mt][nt][3] + bb.y);
            if (MODE == 1) {
                const int which = col >> 10;
                const int h  = (col >> 6) & 15;
                const int dd = col & 63;
                float* dst = (which == 0) ? g_q : (which == 1) ? g_k : g_v;
                const int b0i = row >> 11, s0i = row & 2047;
                *(float2*)&dst[((size_t)((b0i << 4) + h) * SEQ + s0i) * HEAD_DIM + dd] = o0;
                const int r1 = row + 8;
                const int b1i = r1 >> 11, s1i = r1 & 2047;
                *(float2*)&dst[((size_t)((b1i << 4) + h) * SEQ + s1i) * HEAD_DIM + dd] = o1;
            } else {
                *(float2*)&C[(size_t)row * N + col] = o0;
                *(float2*)&C[(size_t)(row + 8) * N + col] = o1;
            }
        }
    }
}

// =======================================================================
// Flash attention on HMMA, split-bf16 (causal).
// CTA: 128 q-rows x one (b,h). 8 warps, 16 rows each. KV tile = 64.
// =======================================================================
#define LDK     72                           // bf16 elems/row (64 + 8 pad)
#define KBUF_E  (64 * LDK)                   // 4608 elems per matrix buffer
#define FSTAGE_E (4 * KBUF_E)                // Khi,Klo,Vhi,Vlo
#define FA_SMEM (2 * FSTAGE_E * 2)           // 73728 bytes

__global__ __launch_bounds__(256, 1)
void fattn()
{
    extern __shared__ char smc[];
    __nv_bfloat16* sb16 = (__nv_bfloat16*)smc;
    const uint32_t sb = smem_u32(smc);

    const int tid  = threadIdx.x;
    const int lane = tid & 31;
    const int wid  = tid >> 5;
    const int wm16 = wid * 16;
    const int bi   = blockIdx.x;
    const int bh   = blockIdx.y;
    const int q0   = bi * 128;

    const float* qp = g_q + (size_t)bh * SEQ * HEAD_DIM;
    const float* kp = g_k + (size_t)bh * SEQ * HEAD_DIM;
    const float* vp = g_v + (size_t)bh * SEQ * HEAD_DIM;

    // ---- stage Q (pre-scaled) hi/lo into smem (occupies stage0 area) ----
#pragma unroll
    for (int r = 0; r < 8; ++r) {
        const int idx = r * 256 + tid;        // 0..2047
        const int row = idx >> 4;             // 0..127
        const int c4  = idx & 15;
        float4 v = *(const float4*)(qp + (size_t)(q0 + row) * HEAD_DIM + c4 * 4);
        v.x *= 0.125f; v.y *= 0.125f; v.z *= 0.125f; v.w *= 0.125f;
        uint2 hi, lo;
        cvt_split(v, hi, lo);
        const int off = row * LDK + c4 * 4;
        *(uint2*)(sb16 + off) = hi;                       // Qhi: elems [0, 2*KBUF_E)
        *(uint2*)(sb16 + 2 * KBUF_E + off) = lo;          // Qlo
    }
    __syncthreads();

    // ---- Q fragments into registers (persist whole loop) ----
    uint32_t qh[4][4], ql[4][4];
#pragma unroll
    for (int kk = 0; kk < 4; ++kk) {
        const uint32_t ao = (uint32_t)(((wm16 + (lane & 15)) * LDK + kk * 16 + (lane >> 4) * 8) * 2);
        ldmx4(qh[kk], sb + ao);
        ldmx4(ql[kk], sb + 2 * KBUF_E * 2 + ao);
    }
    __syncthreads();   // smem free for KV now

    // ---- KV loader mappings ----
    int krow[4], kc4[4];
#pragma unroll
    for (int r = 0; r < 4; ++r) {
        const int idx = r * 256 + tid;        // 0..1023
        krow[r] = idx >> 4;                   // 0..63
        kc4[r]  = idx & 15;
    }

    const int ntiles = 2 * (bi + 1);
    float4 pk[4], pv[4];

    // prologue: tile 0
#pragma unroll
    for (int r = 0; r < 4; ++r) {
        pk[r] = *(const float4*)(kp + (size_t)krow[r] * HEAD_DIM + kc4[r] * 4);
        pv[r] = *(const float4*)(vp + (size_t)krow[r] * HEAD_DIM + kc4[r] * 4);
    }
    {
        __nv_bfloat16* st = sb16;             // stage 0
#pragma unroll
        for (int r = 0; r < 4; ++r) {
            uint2 hi, lo;
            const int off = krow[r] * LDK + kc4[r] * 4;
            cvt_split(pk[r], hi, lo);
            *(uint2*)(st + 0 * KBUF_E + off) = hi;
            *(uint2*)(st + 1 * KBUF_E + off) = lo;
            cvt_split(pv[r], hi, lo);
            *(uint2*)(st + 2 * KBUF_E + off) = hi;
            *(uint2*)(st + 3 * KBUF_E + off) = lo;
        }
    }
    __syncthreads();

    float O[8][4];
#pragma unroll
    for (int nt = 0; nt < 8; ++nt)
#pragma unroll
        for (int r = 0; r < 4; ++r) O[nt][r] = 0.f;
    float m0 = -INFINITY, m1 = -INFINITY, l0 = 0.f, l1 = 0.f;

    const int g  = lane >> 2;
    const int c2 = (lane & 3) * 2;
    const int r0g = q0 + wm16 + g;
    const int r1g = r0g + 8;

    // ldmatrix address offsets (elem units within a matrix buffer)
    const int kb_eoff = ((lane & 7) + ((lane >> 4) & 1) * 8) * LDK + ((lane >> 3) & 1) * 8;
    const int vb_eoff = (((lane >> 3) & 1) * 8 + (lane & 7)) * LDK + (lane >> 4) * 8;

    for (int t = 0; t < ntiles; ++t) {
        const int s = t & 1;
        const uint32_t stg = sb + (uint32_t)(s * FSTAGE_E * 2);

        if (t + 1 < ntiles) {
            const int kv0 = (t + 1) * 64;
#pragma unroll
            for (int r = 0; r < 4; ++r) {
                pk[r] = *(const float4*)(kp + (size_t)(kv0 + krow[r]) * HEAD_DIM + kc4[r] * 4);
                pv[r] = *(const float4*)(vp + (size_t)(kv0 + krow[r]) * HEAD_DIM + kc4[r] * 4);
            }
        }

        // ---- S = Q @ K^T ----
        float S[8][4];
#pragma unroll
        for (int nt = 0; nt < 8; ++nt)
#pragma unroll
            for (int r = 0; r < 4; ++r) S[nt][r] = 0.f;

#pragma unroll
        for (int kk = 0; kk < 4; ++kk) {
#pragma unroll
            for (int ng = 0; ng < 4; ++ng) {
                uint32_t bh_[4], bl_[4];
                const uint32_t bo = (uint32_t)((ng * 16 * LDK + kb_eoff + kk * 16) * 2);
                ldmx4(bh_, stg + 0 * KBUF_E * 2 + bo);
                ldmx4(bl_, stg + 1 * KBUF_E * 2 + bo);
                mma_bf16(S[2 * ng],     qh[kk], bh_[0], bh_[1]);
                mma_bf16(S[2 * ng],     qh[kk], bl_[0], bl_[1]);
                mma_bf16(S[2 * ng],     ql[kk], bh_[0], bh_[1]);
                mma_bf16(S[2 * ng + 1], qh[kk], bh_[2], bh_[3]);
                mma_bf16(S[2 * ng + 1], qh[kk], bl_[2], bl_[3]);
                mma_bf16(S[2 * ng + 1], ql[kk], bh_[2], bh_[3]);
            }
        }

        // ---- causal mask on last two tiles ----
        if (t >= ntiles - 2) {
            const int base = t * 64 + c2;
#pragma unroll
            for (int nt = 0; nt < 8; ++nt) {
                const int col = base + nt * 8;
                if (col     > r0g) S[nt][0] = -INFINITY;
                if (col + 1 > r0g) S[nt][1] = -INFINITY;
                if (col     > r1g) S[nt][2] = -INFINITY;
                if (col + 1 > r1g) S[nt][3] = -INFINITY;
            }
        }

        // ---- online softmax ----
        float mt0 = -INFINITY, mt1 = -INFINITY;
#pragma unroll
        for (int nt = 0; nt < 8; ++nt) {
            mt0 = fmaxf(mt0, fmaxf(S[nt][0], S[nt][1]));
            mt1 = fmaxf(mt1, fmaxf(S[nt][2], S[nt][3]));
        }
        mt0 = fmaxf(mt0, __shfl_xor_sync(0xffffffffu, mt0, 1));
        mt0 = fmaxf(mt0, __shfl_xor_sync(0xffffffffu, mt0, 2));
        mt1 = fmaxf(mt1, __shfl_xor_sync(0xffffffffu, mt1, 1));
        mt1 = fmaxf(mt1, __shfl_xor_sync(0xffffffffu, mt1, 2));

        const float mn0 = fmaxf(m0, mt0);
        const float mn1 = fmaxf(m1, mt1);
        const float corr0 = __expf(m0 - mn0);
        const float corr1 = __expf(m1 - mn1);

        float ps0 = 0.f, ps1 = 0.f;
#pragma unroll
        for (int nt = 0; nt < 8; ++nt) {
            S[nt][0] = __expf(S[nt][0] - mn0);
            S[nt][1] = __expf(S[nt][1] - mn0);
            S[nt][2] = __expf(S[nt][2] - mn1);
            S[nt][3] = __expf(S[nt][3] - mn1);
            ps0 += S[nt][0] + S[nt][1];
            ps1 += S[nt][2] + S[nt][3];
        }
        ps0 += __shfl_xor_sync(0xffffffffu, ps0, 1);
        ps0 += __shfl_xor_sync(0xffffffffu, ps0, 2);
        ps1 += __shfl_xor_sync(0xffffffffu, ps1, 1);
        ps1 += __shfl_xor_sync(0xffffffffu, ps1, 2);

        l0 = l0 * corr0 + ps0;  m0 = mn0;
        l1 = l1 * corr1 + ps1;  m1 = mn1;
#pragma unroll
        for (int nt = 0; nt < 8; ++nt) {
            O[nt][0] *= corr0;  O[nt][1] *= corr0;
            O[nt][2] *= corr1;  O[nt][3] *= corr1;
        }

        // ---- O += P @ V (split P, split V) ----
#pragma unroll
        for (int kk = 0; kk < 4; ++kk) {
            uint32_t ph[4], pl[4];
            pack_split2(S[2 * kk][0],     S[2 * kk][1],     ph[0], pl[0]);
            pack_split2(S[2 * kk][2],     S[2 * kk][3],     ph[1], pl[1]);
            pack_split2(S[2 * kk + 1][0], S[2 * kk + 1][1], ph[2], pl[2]);
            pack_split2(S[2 * kk + 1][2], S[2 * kk + 1][3], ph[3], pl[3]);
#pragma unroll
            for (int ng = 0; ng < 4; ++ng) {
                uint32_t vh_[4], vl_[4];
                const uint32_t vo = (uint32_t)(((kk * 16) * LDK + vb_eoff + ng * 16) * 2);
                ldmx4t(vh_, stg + 2 * KBUF_E * 2 + vo);
                ldmx4t(vl_, stg + 3 * KBUF_E * 2 + vo);
                mma_bf16(O[2 * ng],     ph, vh_[0], vh_[1]);
                mma_bf16(O[2 * ng],     ph, vl_[0], vl_[1]);
                mma_bf16(O[2 * ng],     pl, vh_[0], vh_[1]);
                mma_bf16(O[2 * ng + 1], ph, vh_[2], vh_[3]);
                mma_bf16(O[2 * ng + 1], ph, vl_[2], vl_[3]);
                mma_bf16(O[2 * ng + 1], pl, vh_[2], vh_[3]);
            }
        }

        // ---- stage next tile ----
        if (t + 1 < ntiles) {
            __nv_bfloat16* st = sb16 + (s ^ 1) * FSTAGE_E;
#pragma unroll
            for (int r = 0; r < 4; ++r) {
                uint2 hi, lo;
                const int off = krow[r] * LDK + kc4[r] * 4;
                cvt_split(pk[r], hi, lo);
                *(uint2*)(st + 0 * KBUF_E + off) = hi;
                *(uint2*)(st + 1 * KBUF_E + off) = lo;
                cvt_split(pv[r], hi, lo);
                *(uint2*)(st + 2 * KBUF_E + off) = hi;
                *(uint2*)(st + 3 * KBUF_E + off) = lo;
            }
        }
        __syncthreads();
    }

    // ---- epilogue -> g_ctx [B,S,D] ----
    const float inv0 = 1.f / l0;
    const float inv1 = 1.f / l1;
    const int b = bh >> 4;
    const int h = bh & 15;
    const int row0 = q0 + wm16 + g;
#pragma unroll
    for (int nt = 0; nt < 8; ++nt) {
        const int col = h * HEAD_DIM + nt * 8 + c2;
        *(float2*)&g_ctx[((size_t)(b * SEQ + row0)) * D_MODEL + col] =
            make_float2(O[nt][0] * inv0, O[nt][1] * inv0);
        *(float2*)&g_ctx[((size_t)(b * SEQ + row0 + 8)) * D_MODEL + col] =
            make_float2(O[nt][2] * inv1, O[nt][3] * inv1);
    }
}

// =======================================================================
// launch
// =======================================================================
extern "C" void kernel_launch(void* const* d_in, const int* in_sizes, int n_in,
                              void* d_out, int out_size)
{
    const float* x     = (const float*)d_in[0];
    const float* qkv_w = (const float*)d_in[1];
    const float* qkv_b = (const float*)d_in[2];
    const float* out_w = (const float*)d_in[3];
    const float* out_b = (const float*)d_in[4];
    float* out = (float*)d_out;

    static int attr_set = 0;
    if (!attr_set) {
        cudaFuncSetAttribute(hgemm<1>, cudaFuncAttributeMaxDynamicSharedMemorySize, HG_SMEM);
        cudaFuncSetAttribute(hgemm<2>, cudaFuncAttributeMaxDynamicSharedMemorySize, HG_SMEM);
        cudaFuncSetAttribute(fattn,    cudaFuncAttributeMaxDynamicSharedMemorySize, FA_SMEM);
        attr_set = 1;
    }

    // 1) QKV projection (HMMA split-bf16) + scatter to [B,H,S,hd]
    {
        dim3 grid(QKV_N / 128, M_ROWS / 128);
        hgemm<1><<<grid, 256, HG_SMEM>>>(x, qkv_w, qkv_b, nullptr, QKV_N, D_MODEL);
    }

    // 2) causal flash attention (HMMA split-bf16) -> g_ctx [B,S,D]
    {
        dim3 grid(SEQ / 128, BATCH * NUM_HEADS);
        fattn<<<grid, 256, FA_SMEM>>>();
    }

    // 3) output projection (HMMA split-bf16)
    {
        dim3 grid(D_MODEL / 128, M_ROWS / 128);
        hgemm<2><<<grid, 256, HG_SMEM>>>(nullptr, out_w, out_b, out, D_MODEL, D_MODEL);
    }
}